// round 1
// baseline (speedup 1.0000x reference)
#include <cuda_runtime.h>

// Problem constants
#define Bc 4
#define Tc 4096
#define Ec 2048
#define Hc 16
#define Dc 128
#define NR (Bc * Tc)          // 16384 rows
#define TSPLIT 8
#define TCHUNK (Tc / TSPLIT)  // 512

// Scratch (device globals: allocation-free per harness rules)
__device__ float g_Q[(size_t)NR * Ec];
__device__ float g_K[(size_t)NR * Ec];
__device__ float g_V[(size_t)NR * Ec];
__device__ float g_attn[(size_t)NR * Ec];
__device__ float g_KVp[(size_t)TSPLIT * Bc * Hc * Dc * Dc];  // partial KV per T-chunk
__device__ float g_KV[(size_t)Bc * Hc * Dc * Dc];

// ---------------------------------------------------------------------------
// Generic C = A @ W^T + bias   (A: [M,K] row-major, W: [N,K] row-major)
// 128x128 block tile, BK=16, 256 threads, 8x8 per-thread microtile.
// ---------------------------------------------------------------------------
__global__ __launch_bounds__(256) void gemm_nt_bias(
    const float* __restrict__ A, const float* __restrict__ W,
    const float* __restrict__ bias, float* __restrict__ C,
    int M, int N, int K)
{
    __shared__ float As[16][128];
    __shared__ float Bs[16][128];

    const int tid = threadIdx.x;
    const int tx = tid & 15;   // 0..15 col group
    const int ty = tid >> 4;   // 0..15 row group
    const int rowBase = blockIdx.y * 128;
    const int colBase = blockIdx.x * 128;

    // Load mapping: 512 float4 per tile, 2 per thread
    const int r0 = tid >> 2;          // 0..63
    const int c0 = (tid & 3) * 4;     // 0,4,8,12
    const int r1 = r0 + 64;

    const float* Ar0 = A + (size_t)(rowBase + r0) * K + c0;
    const float* Ar1 = A + (size_t)(rowBase + r1) * K + c0;
    const float* Wr0 = W + (size_t)(colBase + r0) * K + c0;
    const float* Wr1 = W + (size_t)(colBase + r1) * K + c0;

    float acc[8][8] = {};

    for (int k0 = 0; k0 < K; k0 += 16) {
        float4 a0 = *(const float4*)(Ar0 + k0);
        float4 a1 = *(const float4*)(Ar1 + k0);
        float4 w0 = *(const float4*)(Wr0 + k0);
        float4 w1 = *(const float4*)(Wr1 + k0);

        As[c0 + 0][r0] = a0.x; As[c0 + 1][r0] = a0.y;
        As[c0 + 2][r0] = a0.z; As[c0 + 3][r0] = a0.w;
        As[c0 + 0][r1] = a1.x; As[c0 + 1][r1] = a1.y;
        As[c0 + 2][r1] = a1.z; As[c0 + 3][r1] = a1.w;
        Bs[c0 + 0][r0] = w0.x; Bs[c0 + 1][r0] = w0.y;
        Bs[c0 + 2][r0] = w0.z; Bs[c0 + 3][r0] = w0.w;
        Bs[c0 + 0][r1] = w1.x; Bs[c0 + 1][r1] = w1.y;
        Bs[c0 + 2][r1] = w1.z; Bs[c0 + 3][r1] = w1.w;
        __syncthreads();

        #pragma unroll
        for (int kk = 0; kk < 16; kk++) {
            float a[8], b[8];
            *(float4*)&a[0] = *(const float4*)&As[kk][ty * 8];
            *(float4*)&a[4] = *(const float4*)&As[kk][ty * 8 + 4];
            *(float4*)&b[0] = *(const float4*)&Bs[kk][tx * 8];
            *(float4*)&b[4] = *(const float4*)&Bs[kk][tx * 8 + 4];
            #pragma unroll
            for (int i = 0; i < 8; i++)
                #pragma unroll
                for (int j = 0; j < 8; j++)
                    acc[i][j] += a[i] * b[j];
        }
        __syncthreads();
    }

    const int col = colBase + tx * 8;
    float4 bv0 = *(const float4*)&bias[col];
    float4 bv1 = *(const float4*)&bias[col + 4];
    #pragma unroll
    for (int i = 0; i < 8; i++) {
        size_t row = (size_t)(rowBase + ty * 8 + i);
        float4 o0 = make_float4(acc[i][0] + bv0.x, acc[i][1] + bv0.y,
                                acc[i][2] + bv0.z, acc[i][3] + bv0.w);
        float4 o1 = make_float4(acc[i][4] + bv1.x, acc[i][5] + bv1.y,
                                acc[i][6] + bv1.z, acc[i][7] + bv1.w);
        *(float4*)&C[row * N + col]     = o0;
        *(float4*)&C[row * N + col + 4] = o1;
    }
}

// ---------------------------------------------------------------------------
// KV partial: for (b,h), T-chunk s: KVp[s,bh,d,e] = sum_{t in chunk} K[t,d]*V[t,e]
// Block computes the full 128x128 tile over a 512-long T chunk.
// ---------------------------------------------------------------------------
__global__ __launch_bounds__(256) void kv_partial()
{
    const int bh = blockIdx.x;             // 0..63
    const int b = bh >> 4, h = bh & 15;
    const int t0 = blockIdx.y * TCHUNK;

    __shared__ float Ks[16][128];
    __shared__ float Vs[16][128];

    const int tid = threadIdx.x;
    const int tx = tid & 15;
    const int ty = tid >> 4;
    const int r0 = tid >> 5;               // 0..7
    const int c0 = (tid & 31) * 4;         // 0..124
    const int r1 = r0 + 8;

    const float* Kb = g_K + ((size_t)b * Tc + t0) * Ec + (size_t)h * Dc;
    const float* Vb = g_V + ((size_t)b * Tc + t0) * Ec + (size_t)h * Dc;

    float acc[8][8] = {};

    for (int tt = 0; tt < TCHUNK; tt += 16) {
        *(float4*)&Ks[r0][c0] = *(const float4*)&Kb[(size_t)(tt + r0) * Ec + c0];
        *(float4*)&Ks[r1][c0] = *(const float4*)&Kb[(size_t)(tt + r1) * Ec + c0];
        *(float4*)&Vs[r0][c0] = *(const float4*)&Vb[(size_t)(tt + r0) * Ec + c0];
        *(float4*)&Vs[r1][c0] = *(const float4*)&Vb[(size_t)(tt + r1) * Ec + c0];
        __syncthreads();

        #pragma unroll
        for (int kk = 0; kk < 16; kk++) {
            float a[8], b2[8];
            *(float4*)&a[0]  = *(const float4*)&Ks[kk][ty * 8];
            *(float4*)&a[4]  = *(const float4*)&Ks[kk][ty * 8 + 4];
            *(float4*)&b2[0] = *(const float4*)&Vs[kk][tx * 8];
            *(float4*)&b2[4] = *(const float4*)&Vs[kk][tx * 8 + 4];
            #pragma unroll
            for (int i = 0; i < 8; i++)
                #pragma unroll
                for (int j = 0; j < 8; j++)
                    acc[i][j] += a[i] * b2[j];
        }
        __syncthreads();
    }

    float* outp = g_KVp + ((size_t)blockIdx.y * (Bc * Hc) + bh) * (Dc * Dc);
    #pragma unroll
    for (int i = 0; i < 8; i++) {
        int d = ty * 8 + i;
        *(float4*)&outp[(size_t)d * Dc + tx * 8]     = *(float4*)&acc[i][0];
        *(float4*)&outp[(size_t)d * Dc + tx * 8 + 4] = *(float4*)&acc[i][4];
    }
}

// Deterministic reduce of the 8 partials
__global__ __launch_bounds__(256) void kv_reduce()
{
    const size_t idx = (size_t)blockIdx.x * 256 + threadIdx.x;  // < 64*128*128
    float s = 0.f;
    #pragma unroll
    for (int p = 0; p < TSPLIT; p++)
        s += g_KVp[(size_t)p * (Bc * Hc * Dc * Dc) + idx];
    g_KV[idx] = s;
}

// ---------------------------------------------------------------------------
// attn[b,t,h,:] = scale * Q[b,t,h,:] @ KV[b,h]
// ---------------------------------------------------------------------------
__global__ __launch_bounds__(256) void attn_apply()
{
    const int bh = blockIdx.y;
    const int b = bh >> 4, h = bh & 15;
    const int t0 = blockIdx.x * 128;

    __shared__ float Qs[16][128];   // transposed: Qs[d][t]
    __shared__ float Cs[16][128];   // KV natural: Cs[d][e]

    const int tid = threadIdx.x;
    const int tx = tid & 15;
    const int ty = tid >> 4;

    const int qr0 = tid >> 2, qc0 = (tid & 3) * 4, qr1 = qr0 + 64;
    const int kr0 = tid >> 5, kc0 = (tid & 31) * 4, kr1 = kr0 + 8;

    const float* Qb  = g_Q + ((size_t)b * Tc + t0) * Ec + (size_t)h * Dc;
    const float* KVb = g_KV + (size_t)bh * Dc * Dc;

    float acc[8][8] = {};

    for (int k0 = 0; k0 < Dc; k0 += 16) {
        float4 q0 = *(const float4*)&Qb[(size_t)qr0 * Ec + k0 + qc0];
        float4 q1 = *(const float4*)&Qb[(size_t)qr1 * Ec + k0 + qc0];
        Qs[qc0 + 0][qr0] = q0.x; Qs[qc0 + 1][qr0] = q0.y;
        Qs[qc0 + 2][qr0] = q0.z; Qs[qc0 + 3][qr0] = q0.w;
        Qs[qc0 + 0][qr1] = q1.x; Qs[qc0 + 1][qr1] = q1.y;
        Qs[qc0 + 2][qr1] = q1.z; Qs[qc0 + 3][qr1] = q1.w;
        *(float4*)&Cs[kr0][kc0] = *(const float4*)&KVb[(size_t)(k0 + kr0) * Dc + kc0];
        *(float4*)&Cs[kr1][kc0] = *(const float4*)&KVb[(size_t)(k0 + kr1) * Dc + kc0];
        __syncthreads();

        #pragma unroll
        for (int kk = 0; kk < 16; kk++) {
            float a[8], b2[8];
            *(float4*)&a[0]  = *(const float4*)&Qs[kk][ty * 8];
            *(float4*)&a[4]  = *(const float4*)&Qs[kk][ty * 8 + 4];
            *(float4*)&b2[0] = *(const float4*)&Cs[kk][tx * 8];
            *(float4*)&b2[4] = *(const float4*)&Cs[kk][tx * 8 + 4];
            #pragma unroll
            for (int i = 0; i < 8; i++)
                #pragma unroll
                for (int j = 0; j < 8; j++)
                    acc[i][j] += a[i] * b2[j];
        }
        __syncthreads();
    }

    const float scale = 0.088388347648318447f;  // 1/sqrt(128)
    float* Ob = g_attn + ((size_t)b * Tc + t0) * Ec + (size_t)h * Dc;
    #pragma unroll
    for (int i = 0; i < 8; i++) {
        size_t row = (size_t)(ty * 8 + i);
        float4 o0 = make_float4(acc[i][0] * scale, acc[i][1] * scale,
                                acc[i][2] * scale, acc[i][3] * scale);
        float4 o1 = make_float4(acc[i][4] * scale, acc[i][5] * scale,
                                acc[i][6] * scale, acc[i][7] * scale);
        *(float4*)&Ob[row * Ec + tx * 8]     = o0;
        *(float4*)&Ob[row * Ec + tx * 8 + 4] = o1;
    }
}

// ---------------------------------------------------------------------------
extern "C" void kernel_launch(void* const* d_in, const int* in_sizes, int n_in,
                              void* d_out, int out_size)
{
    const float* x  = (const float*)d_in[0];
    const float* Wq = (const float*)d_in[1];
    const float* bq = (const float*)d_in[2];
    const float* Wk = (const float*)d_in[3];
    const float* bk = (const float*)d_in[4];
    const float* Wv = (const float*)d_in[5];
    const float* bv = (const float*)d_in[6];
    const float* Wo = (const float*)d_in[7];
    const float* bo = (const float*)d_in[8];
    float* out = (float*)d_out;

    float *Qp, *Kp, *Vp, *Ap;
    cudaGetSymbolAddress((void**)&Qp, g_Q);
    cudaGetSymbolAddress((void**)&Kp, g_K);
    cudaGetSymbolAddress((void**)&Vp, g_V);
    cudaGetSymbolAddress((void**)&Ap, g_attn);

    dim3 blk(256);
    dim3 gP(Ec / 128, NR / 128);   // (16, 128)

    gemm_nt_bias<<<gP, blk>>>(x, Wq, bq, Qp, NR, Ec, Ec);
    gemm_nt_bias<<<gP, blk>>>(x, Wk, bk, Kp, NR, Ec, Ec);
    gemm_nt_bias<<<gP, blk>>>(x, Wv, bv, Vp, NR, Ec, Ec);

    kv_partial<<<dim3(Bc * Hc, TSPLIT), blk>>>();
    kv_reduce<<<(Bc * Hc * Dc * Dc) / 256, blk>>>();

    attn_apply<<<dim3(Tc / 128, Bc * Hc), blk>>>();

    gemm_nt_bias<<<gP, blk>>>(Ap, Wo, bo, out, NR, Ec, Ec);
}